// round 6
// baseline (speedup 1.0000x reference)
#include <cuda_runtime.h>
#include <cstddef>
#include <cstdint>

// Problem constants
#define BATCH 2
#define SEQ   2048
#define DMODEL 1024
#define NHEADS 16
#define DHEAD 64
#define MROWS (BATCH*SEQ)        // 4096

// ---------------- scratch (no allocation allowed) ----------------
__device__ float g_q[BATCH*NHEADS*SEQ*DHEAD];   // [B,H,S,Dh]  (tf32-rounded)
__device__ float g_k[BATCH*NHEADS*SEQ*DHEAD];
__device__ float g_v[BATCH*NHEADS*SEQ*DHEAD];
__device__ float g_ao[MROWS*DMODEL];            // attention out (tf32-rounded)
// tf32-rounded copies of inputs
__device__ float g_rx[3][MROWS*DMODEL];         // query/key_/value rounded
__device__ float g_rw[4][DMODEL*DMODEL];        // Wq/Wk/Wv/Wo rounded

// ---------------- helpers ----------------
__device__ __forceinline__ unsigned f2tf32(float x) {
    unsigned u;
    asm("cvt.rna.tf32.f32 %0, %1;" : "=r"(u) : "f"(x));
    return u;
}

__device__ __forceinline__ float cvt_tf32f(float x) {
    unsigned u;
    asm("cvt.rna.tf32.f32 %0, %1;" : "=r"(u) : "f"(x));
    return __uint_as_float(u);
}

__device__ __forceinline__ void mma_tf32(float* c, const unsigned* a, const unsigned* b) {
    asm volatile(
        "mma.sync.aligned.m16n8k8.row.col.f32.tf32.tf32.f32 "
        "{%0,%1,%2,%3}, {%4,%5,%6,%7}, {%8,%9}, {%0,%1,%2,%3};"
        : "+f"(c[0]), "+f"(c[1]), "+f"(c[2]), "+f"(c[3])
        : "r"(a[0]), "r"(a[1]), "r"(a[2]), "r"(a[3]),
          "r"(b[0]), "r"(b[1]));
}

__device__ __forceinline__ uint32_t smem_u32(const void* p) {
    uint32_t a;
    asm("{ .reg .u64 t; cvta.to.shared.u64 t, %1; cvt.u32.u64 %0, t; }"
        : "=r"(a) : "l"(p));
    return a;
}

__device__ __forceinline__ void cpa16(uint32_t dst, const void* src) {
    asm volatile("cp.async.cg.shared.global [%0], [%1], 16;"
                 :: "r"(dst), "l"(src) : "memory");
}
#define CPA_COMMIT() asm volatile("cp.async.commit_group;" ::: "memory")
#define CPA_WAIT2()  asm volatile("cp.async.wait_group 2;" ::: "memory")
#define CPA_WAIT1()  asm volatile("cp.async.wait_group 1;" ::: "memory")
#define CPA_WAIT0()  asm volatile("cp.async.wait_group 0;" ::: "memory")

// ---------------- pre-round: out = tf32_rna(in), element-wise --------------
__global__ __launch_bounds__(256) void round_tf32(
    const float* __restrict__ in, float* __restrict__ out, int n4)
{
    int i = blockIdx.x * 256 + threadIdx.x;
    if (i < n4) {
        float4 v = ((const float4*)in)[i];
        v.x = cvt_tf32f(v.x); v.y = cvt_tf32f(v.y);
        v.z = cvt_tf32f(v.z); v.w = cvt_tf32f(v.w);
        ((float4*)out)[i] = v;
    }
}

// ---------------- GEMM (tf32 mma, 3-stage cp.async): Y = X @ W^T + b -------
// Tile 128x128x32, 256 threads (8 warps: 4m x 2n). X/W pre-rounded to tf32.
// split==1: write [B,H,S,Dh], rounded.  split==0: plain [M,N], raw fp32.
#define GP 36
#define G_STAGE 9216                    // floats per stage (A 4608 + B 4608)
#define G_SMEM_FLOATS (3 * G_STAGE)     // 27648 floats = 110592 bytes

__global__ __launch_bounds__(256) void gemm_tf32(
    const float* __restrict__ X, const float* __restrict__ W,
    const float* __restrict__ bias, float* __restrict__ Y, int split)
{
    extern __shared__ float sg[];
    const uint32_t smb = smem_u32(sg);

    const int t    = threadIdx.x;
    const int lane = t & 31;
    const int wid  = t >> 5;
    const int gid  = lane >> 2;
    const int tg   = lane & 3;

    const int bm = blockIdx.y * 128;
    const int bn = blockIdx.x * 128;
    const int m_base = (wid >> 1) * 32;
    const int n_base = (wid & 1) * 64;

    float acc[2][8][4];
    #pragma unroll
    for (int mt = 0; mt < 2; mt++)
        #pragma unroll
        for (int nt = 0; nt < 8; nt++)
            #pragma unroll
            for (int i = 0; i < 4; i++) acc[mt][nt][i] = 0.f;

    const int pr = t >> 1;             // copy row 0..127
    const int pq = (t & 1) * 16;       // byte col base within 128B row half
    (void)pr; (void)pq;

    // prologue: prefetch chunks 0,1 into stages 0,1
    #pragma unroll
    for (int p = 0; p < 2; p++) {
        const int aoff = p * G_STAGE;
        const int boff = p * G_STAGE + 4608;
        const float* xs = X + (size_t)bm * DMODEL + p * 32;
        const float* ws = W + (size_t)bn * DMODEL + p * 32;
        #pragma unroll
        for (int l = 0; l < 4; l++) {
            int id = t + 256 * l;
            int r  = id >> 3, q = id & 7;
            cpa16(smb + (uint32_t)(aoff + r * GP + q * 4) * 4,
                  xs + (size_t)r * DMODEL + q * 4);
            cpa16(smb + (uint32_t)(boff + r * GP + q * 4) * 4,
                  ws + (size_t)r * DMODEL + q * 4);
        }
        CPA_COMMIT();
    }

    for (int c = 0; c < 32; c++) {
        const int stage = c % 3;
        const int aoff  = stage * G_STAGE;
        const int boff  = stage * G_STAGE + 4608;

        if (c + 2 < 32) {
            const int ns    = (c + 2) % 3;
            const int naof  = ns * G_STAGE;
            const int nbof  = ns * G_STAGE + 4608;
            const int k0    = (c + 2) * 32;
            const float* xs = X + (size_t)bm * DMODEL + k0;
            const float* ws = W + (size_t)bn * DMODEL + k0;
            #pragma unroll
            for (int l = 0; l < 4; l++) {
                int id = t + 256 * l;
                int r  = id >> 3, q = id & 7;
                cpa16(smb + (uint32_t)(naof + r * GP + q * 4) * 4,
                      xs + (size_t)r * DMODEL + q * 4);
                cpa16(smb + (uint32_t)(nbof + r * GP + q * 4) * 4,
                      ws + (size_t)r * DMODEL + q * 4);
            }
            CPA_COMMIT();
            CPA_WAIT2();
        } else if (c + 1 < 32) {
            CPA_WAIT1();
        } else {
            CPA_WAIT0();
        }
        __syncthreads();

        const float* As = sg + aoff;
        const float* Bs = sg + boff;
        #pragma unroll
        for (int ks = 0; ks < 4; ks++) {
            const int kb = ks * 8;
            unsigned afr[2][4];
            #pragma unroll
            for (int mt = 0; mt < 2; mt++) {
                int m = m_base + mt * 16;
                afr[mt][0] = __float_as_uint(As[(m + gid    ) * GP + kb + tg    ]);
                afr[mt][1] = __float_as_uint(As[(m + gid + 8) * GP + kb + tg    ]);
                afr[mt][2] = __float_as_uint(As[(m + gid    ) * GP + kb + 4 + tg]);
                afr[mt][3] = __float_as_uint(As[(m + gid + 8) * GP + kb + 4 + tg]);
            }
            unsigned bfr[8][2];
            #pragma unroll
            for (int nt = 0; nt < 8; nt++) {
                int n = n_base + nt * 8;
                bfr[nt][0] = __float_as_uint(Bs[(n + gid) * GP + kb + tg    ]);
                bfr[nt][1] = __float_as_uint(Bs[(n + gid) * GP + kb + 4 + tg]);
            }
            #pragma unroll
            for (int mt = 0; mt < 2; mt++)
                #pragma unroll
                for (int nt = 0; nt < 8; nt++)
                    mma_tf32(acc[mt][nt], afr[mt], bfr[nt]);
        }
        __syncthreads();   // stage gets overwritten by prefetch of c+3 next iter
    }

    // epilogue
    #pragma unroll
    for (int nt = 0; nt < 8; nt++) {
        int c0 = bn + n_base + nt * 8 + tg * 2;
        float b0 = bias[c0], b1 = bias[c0 + 1];
        #pragma unroll
        for (int mt = 0; mt < 2; mt++) {
            int r0 = bm + m_base + mt * 16 + gid;
            #pragma unroll
            for (int half = 0; half < 2; half++) {
                int m = r0 + half * 8;
                float v0 = acc[mt][nt][half * 2 + 0] + b0;
                float v1 = acc[mt][nt][half * 2 + 1] + b1;
                if (!split) {
                    Y[(size_t)m * DMODEL + c0]     = v0;
                    Y[(size_t)m * DMODEL + c0 + 1] = v1;
                } else {
                    int b_ = m >> 11;
                    int s  = m & (SEQ - 1);
                    int h  = c0 >> 6;
                    int dh = c0 & (DHEAD - 1);
                    size_t base = (((size_t)(b_ * NHEADS + h)) * SEQ + s) * DHEAD;
                    Y[base + dh]     = cvt_tf32f(v0);   // pre-round for attn
                    Y[base + dh + 1] = cvt_tf32f(v1);
                }
            }
        }
    }
}

// ---------------- attention: register flash + cp.async double buffer ------
// Inputs Q/K/V already tf32-rounded by QKV GEMM epilogue.
// Softmax in base-2: Q scaled by 0.125*log2(e), exp2 replaces exp.
#define KP 68
#define VP 72
#define A_K0 0
#define A_V0 4352
#define A_K1 8960
#define A_V1 13312
#define A_SMEM_FLOATS 17920    // 71680 bytes

#define LOG2E 1.44269504088896340736f

__global__ __launch_bounds__(256) void attn_kernel(
    const float* __restrict__ Q, const float* __restrict__ K,
    const float* __restrict__ V, float* __restrict__ O)
{
    extern __shared__ float sm[];
    const uint32_t smb = smem_u32(sm);

    const int t    = threadIdx.x;
    const int lane = t & 31;
    const int wid  = t >> 5;
    const int gid  = lane >> 2;
    const int tg   = lane & 3;

    const int b  = blockIdx.z, h = blockIdx.y;
    const int q0 = blockIdx.x << 7;
    const size_t head_base = ((size_t)(b * NHEADS + h)) * SEQ * DHEAD;

    // ---- stage Q (scaled 0.125*log2e, tf32) into smem, extract frags ----
    {
        float (*Qs)[KP] = (float (*)[KP])sm;
        const float qs = 0.125f * LOG2E;
        #pragma unroll
        for (int l = 0; l < 8; l++) {
            int id = t + 256 * l;
            int r  = id >> 4;
            int d4 = (id & 15) << 2;
            float4 v = *(const float4*)&Q[head_base + (size_t)(q0 + r) * DHEAD + d4];
            Qs[r][d4+0] = cvt_tf32f(v.x * qs);
            Qs[r][d4+1] = cvt_tf32f(v.y * qs);
            Qs[r][d4+2] = cvt_tf32f(v.z * qs);
            Qs[r][d4+3] = cvt_tf32f(v.w * qs);
        }
    }
    __syncthreads();

    unsigned qf[8][4];
    {
        float (*Qs)[KP] = (float (*)[KP])sm;
        const int wrow = wid * 16;
        #pragma unroll
        for (int ks = 0; ks < 8; ks++) {
            const int kb = ks * 8;
            qf[ks][0] = __float_as_uint(Qs[wrow + gid    ][kb + tg    ]);
            qf[ks][1] = __float_as_uint(Qs[wrow + gid + 8][kb + tg    ]);
            qf[ks][2] = __float_as_uint(Qs[wrow + gid    ][kb + 4 + tg]);
            qf[ks][3] = __float_as_uint(Qs[wrow + gid + 8][kb + 4 + tg]);
        }
    }
    __syncthreads();   // Q reads done before buf0 prefetch overwrites staging

    // ---- prefetch KV tile 0 into buf0 ----
    {
        #pragma unroll
        for (int l = 0; l < 4; l++) {
            int id = t + 256 * l;
            int r  = id >> 4;
            int c4 = (id & 15) << 2;
            cpa16(smb + (uint32_t)(A_K0 + r * KP + c4) * 4,
                  K + head_base + (size_t)r * DHEAD + c4);
            cpa16(smb + (uint32_t)(A_V0 + r * VP + c4) * 4,
                  V + head_base + (size_t)r * DHEAD + c4);
        }
        CPA_COMMIT();
    }

    float oacc[8][4];
    #pragma unroll
    for (int nt = 0; nt < 8; nt++)
        #pragma unroll
        for (int i = 0; i < 4; i++) oacc[nt][i] = 0.f;
    float m0 = -1e30f, m1 = -1e30f, l0 = 0.f, l1 = 0.f;

    const int src1 = (lane & ~3) | (tg >> 1);
    const int src2 = src1 + 2;
    const bool odd = (tg & 1);

    for (int it = 0; it < SEQ / 64; it++) {
        const int koff = (it & 1) ? A_K1 : A_K0;
        const int voff = (it & 1) ? A_V1 : A_V0;

        if (it + 1 < SEQ / 64) {
            const int nk = ((it + 1) & 1) ? A_K1 : A_K0;
            const int nv = ((it + 1) & 1) ? A_V1 : A_V0;
            const size_t gofs = head_base + (size_t)(it + 1) * 64 * DHEAD;
            #pragma unroll
            for (int l = 0; l < 4; l++) {
                int id = t + 256 * l;
                int r  = id >> 4;
                int c4 = (id & 15) << 2;
                cpa16(smb + (uint32_t)(nk + r * KP + c4) * 4,
                      K + gofs + (size_t)r * DHEAD + c4);
                cpa16(smb + (uint32_t)(nv + r * VP + c4) * 4,
                      V + gofs + (size_t)r * DHEAD + c4);
            }
            CPA_COMMIT();
            CPA_WAIT1();
        } else {
            CPA_WAIT0();
        }
        __syncthreads();

        const float* Ks = sm + koff;
        const float* Vs = sm + voff;

        // ---- S2 = (Q*0.125*log2e) K^T  (base-2 scores) ----
        float sacc[8][4];
        #pragma unroll
        for (int nt = 0; nt < 8; nt++)
            #pragma unroll
            for (int i = 0; i < 4; i++) sacc[nt][i] = 0.f;

        #pragma unroll
        for (int ks = 0; ks < 8; ks++) {
            const int kb = ks * 8;
            unsigned bfr[8][2];
            #pragma unroll
            for (int nt = 0; nt < 8; nt++) {
                bfr[nt][0] = __float_as_uint(Ks[(nt * 8 + gid) * KP + kb + tg    ]);
                bfr[nt][1] = __float_as_uint(Ks[(nt * 8 + gid) * KP + kb + 4 + tg]);
            }
            #pragma unroll
            for (int nt = 0; nt < 8; nt++)
                mma_tf32(sacc[nt], qf[ks], bfr[nt]);
        }

        // ---- online softmax in base-2 (regs + quad shuffles) ----
        float mx0 = -1e30f, mx1 = -1e30f;
        #pragma unroll
        for (int nt = 0; nt < 8; nt++) {
            mx0 = fmaxf(mx0, fmaxf(sacc[nt][0], sacc[nt][1]));
            mx1 = fmaxf(mx1, fmaxf(sacc[nt][2], sacc[nt][3]));
        }
        mx0 = fmaxf(mx0, __shfl_xor_sync(0xffffffffu, mx0, 1));
        mx0 = fmaxf(mx0, __shfl_xor_sync(0xffffffffu, mx0, 2));
        mx1 = fmaxf(mx1, __shfl_xor_sync(0xffffffffu, mx1, 1));
        mx1 = fmaxf(mx1, __shfl_xor_sync(0xffffffffu, mx1, 2));

        float m0n = fmaxf(m0, mx0), m1n = fmaxf(m1, mx1);
        float sc0 = exp2f(m0 - m0n), sc1 = exp2f(m1 - m1n);
        m0 = m0n; m1 = m1n;

        float s0 = 0.f, s1 = 0.f;
        #pragma unroll
        for (int nt = 0; nt < 8; nt++) {
            sacc[nt][0] = exp2f(sacc[nt][0] - m0); s0 += sacc[nt][0];
            sacc[nt][1] = exp2f(sacc[nt][1] - m0); s0 += sacc[nt][1];
            sacc[nt][2] = exp2f(sacc[nt][2] - m1); s1 += sacc[nt][2];
            sacc[nt][3] = exp2f(sacc[nt][3] - m1); s1 += sacc[nt][3];
        }
        s0 += __shfl_xor_sync(0xffffffffu, s0, 1);
        s0 += __shfl_xor_sync(0xffffffffu, s0, 2);
        s1 += __shfl_xor_sync(0xffffffffu, s1, 1);
        s1 += __shfl_xor_sync(0xffffffffu, s1, 2);
        l0 = l0 * sc0 + s0;
        l1 = l1 * sc1 + s1;

        #pragma unroll
        for (int nt = 0; nt < 8; nt++) {
            oacc[nt][0] *= sc0; oacc[nt][1] *= sc0;
            oacc[nt][2] *= sc1; oacc[nt][3] *= sc1;
        }

        // ---- PV: P c-frag -> a-frag via quad shuffles, mma with V ----
        #pragma unroll
        for (int ks = 0; ks < 8; ks++) {
            float p0 = sacc[ks][0], p1 = sacc[ks][1];
            float p2 = sacc[ks][2], p3 = sacc[ks][3];
            float v00 = __shfl_sync(0xffffffffu, p0, src1);
            float v01 = __shfl_sync(0xffffffffu, p1, src1);
            float v10 = __shfl_sync(0xffffffffu, p2, src1);
            float v11 = __shfl_sync(0xffffffffu, p3, src1);
            float v20 = __shfl_sync(0xffffffffu, p0, src2);
            float v21 = __shfl_sync(0xffffffffu, p1, src2);
            float v30 = __shfl_sync(0xffffffffu, p2, src2);
            float v31 = __shfl_sync(0xffffffffu, p3, src2);
            unsigned a[4];
            a[0] = f2tf32(odd ? v01 : v00);
            a[1] = f2tf32(odd ? v11 : v10);
            a[2] = f2tf32(odd ? v21 : v20);
            a[3] = f2tf32(odd ? v31 : v30);

            const int kb = ks * 8;
            #pragma unroll
            for (int nt = 0; nt < 8; nt++) {
                unsigned b2[2];
                b2[0] = __float_as_uint(Vs[(kb + tg    ) * VP + nt * 8 + gid]);
                b2[1] = __float_as_uint(Vs[(kb + 4 + tg) * VP + nt * 8 + gid]);
                mma_tf32(oacc[nt], a, b2);
            }
        }
        __syncthreads();   // before next iter's prefetch overwrites this buf
    }

    // ---- epilogue: normalize, write rounded [B,S,D] (O-proj input) ----
    {
        float il0 = 1.0f / l0, il1 = 1.0f / l1;
        int r0 = q0 + wid * 16 + gid;
        int r1 = r0 + 8;
        #pragma unroll
        for (int nt = 0; nt < 8; nt++) {
            int c = h * DHEAD + nt * 8 + tg * 2;
            float2 o0 = make_float2(cvt_tf32f(oacc[nt][0] * il0),
                                    cvt_tf32f(oacc[nt][1] * il0));
            float2 o1 = make_float2(cvt_tf32f(oacc[nt][2] * il1),
                                    cvt_tf32f(oacc[nt][3] * il1));
            *(float2*)&O[((size_t)(b * SEQ + r0)) * DMODEL + c] = o0;
            *(float2*)&O[((size_t)(b * SEQ + r1)) * DMODEL + c] = o1;
        }
    }
}

extern "C" void kernel_launch(void* const* d_in, const int* in_sizes, int n_in,
                              void* d_out, int out_size)
{
    const float* query = (const float*)d_in[0];
    const float* key_  = (const float*)d_in[1];
    const float* value = (const float*)d_in[2];
    const float* Wq = (const float*)d_in[3];
    const float* bq = (const float*)d_in[4];
    const float* Wk = (const float*)d_in[5];
    const float* bk = (const float*)d_in[6];
    const float* Wv = (const float*)d_in[7];
    const float* bv = (const float*)d_in[8];
    const float* Wo = (const float*)d_in[9];
    const float* bo = (const float*)d_in[10];

    float *qptr, *kptr, *vptr, *aoptr, *rxptr, *rwptr;
    cudaGetSymbolAddress((void**)&qptr,  g_q);
    cudaGetSymbolAddress((void**)&kptr,  g_k);
    cudaGetSymbolAddress((void**)&vptr,  g_v);
    cudaGetSymbolAddress((void**)&aoptr, g_ao);
    cudaGetSymbolAddress((void**)&rxptr, g_rx);
    cudaGetSymbolAddress((void**)&rwptr, g_rw);

    float* rq = rxptr;
    float* rk = rxptr + (size_t)MROWS * DMODEL;
    float* rv = rxptr + 2 * (size_t)MROWS * DMODEL;
    float* rwq = rwptr;
    float* rwk = rwptr + (size_t)DMODEL * DMODEL;
    float* rwv = rwptr + 2 * (size_t)DMODEL * DMODEL;
    float* rwo = rwptr + 3 * (size_t)DMODEL * DMODEL;

    const int gemm_smem = G_SMEM_FLOATS * sizeof(float);   // 110592
    const int attn_smem = A_SMEM_FLOATS * sizeof(float);   // 71680
    cudaFuncSetAttribute(gemm_tf32, cudaFuncAttributeMaxDynamicSharedMemorySize, gemm_smem);
    cudaFuncSetAttribute(attn_kernel, cudaFuncAttributeMaxDynamicSharedMemorySize, attn_smem);

    // pre-round inputs & weights to tf32 (removes cvt from all hot loops)
    const int NX4 = MROWS * DMODEL / 4;    // 1M float4
    const int NW4 = DMODEL * DMODEL / 4;   // 256K float4
    round_tf32<<<(NX4 + 255) / 256, 256>>>(query, rq, NX4);
    round_tf32<<<(NX4 + 255) / 256, 256>>>(key_,  rk, NX4);
    round_tf32<<<(NX4 + 255) / 256, 256>>>(value, rv, NX4);
    round_tf32<<<(NW4 + 255) / 256, 256>>>(Wq, rwq, NW4);
    round_tf32<<<(NW4 + 255) / 256, 256>>>(Wk, rwk, NW4);
    round_tf32<<<(NW4 + 255) / 256, 256>>>(Wv, rwv, NW4);
    round_tf32<<<(NW4 + 255) / 256, 256>>>(Wo, rwo, NW4);

    dim3 ggrid(DMODEL / 128, MROWS / 128);   // (8, 32)
    gemm_tf32<<<ggrid, 256, gemm_smem>>>(rq, rwq, bq, qptr, 1);
    gemm_tf32<<<ggrid, 256, gemm_smem>>>(rk, rwk, bk, kptr, 1);
    gemm_tf32<<<ggrid, 256, gemm_smem>>>(rv, rwv, bv, vptr, 1);

    dim3 agrid(SEQ / 128, NHEADS, BATCH);    // (16, 16, 2)
    attn_kernel<<<agrid, 256, attn_smem>>>(qptr, kptr, vptr, aoptr);

    gemm_tf32<<<ggrid, 256, gemm_smem>>>(aoptr, rwo, bo, (float*)d_out, 0);
}

// round 7
// speedup vs baseline: 1.0420x; 1.0420x over previous
#include <cuda_runtime.h>
#include <cstddef>
#include <cstdint>

// Problem constants
#define BATCH 2
#define SEQ   2048
#define DMODEL 1024
#define NHEADS 16
#define DHEAD 64
#define MROWS (BATCH*SEQ)        // 4096

// ---------------- scratch (no allocation allowed) ----------------
__device__ float g_q[BATCH*NHEADS*SEQ*DHEAD];   // [B,H,S,Dh]  (tf32-rounded)
__device__ float g_k[BATCH*NHEADS*SEQ*DHEAD];
__device__ float g_v[BATCH*NHEADS*SEQ*DHEAD];
__device__ float g_ao[MROWS*DMODEL];            // attention out (tf32-rounded)

// ---------------- helpers ----------------
__device__ __forceinline__ unsigned f2tf32(float x) {
    unsigned u;
    asm("cvt.rna.tf32.f32 %0, %1;" : "=r"(u) : "f"(x));
    return u;
}

__device__ __forceinline__ float cvt_tf32f(float x) {
    unsigned u;
    asm("cvt.rna.tf32.f32 %0, %1;" : "=r"(u) : "f"(x));
    return __uint_as_float(u);
}

__device__ __forceinline__ void mma_tf32(float* c, const unsigned* a, const unsigned* b) {
    asm volatile(
        "mma.sync.aligned.m16n8k8.row.col.f32.tf32.tf32.f32 "
        "{%0,%1,%2,%3}, {%4,%5,%6,%7}, {%8,%9}, {%0,%1,%2,%3};"
        : "+f"(c[0]), "+f"(c[1]), "+f"(c[2]), "+f"(c[3])
        : "r"(a[0]), "r"(a[1]), "r"(a[2]), "r"(a[3]),
          "r"(b[0]), "r"(b[1]));
}

__device__ __forceinline__ uint32_t smem_u32(const void* p) {
    uint32_t a;
    asm("{ .reg .u64 t; cvta.to.shared.u64 t, %1; cvt.u32.u64 %0, t; }"
        : "=r"(a) : "l"(p));
    return a;
}

__device__ __forceinline__ void cpa16(uint32_t dst, const void* src) {
    asm volatile("cp.async.cg.shared.global [%0], [%1], 16;"
                 :: "r"(dst), "l"(src) : "memory");
}
#define CPA_COMMIT() asm volatile("cp.async.commit_group;" ::: "memory")
#define CPA_WAIT1()  asm volatile("cp.async.wait_group 1;" ::: "memory")
#define CPA_WAIT0()  asm volatile("cp.async.wait_group 0;" ::: "memory")

// ---------------- GEMM (tf32 mma, 3-stage, 1 sync/iter): Y = X @ W^T + b ---
// Tile 128x128x32, 256 threads (8 warps: 4m x 2n). Raw fp32 in smem,
// RNA conversion at fragment load.
// split==1: write [B,H,S,Dh], rounded.  split==0: plain [M,N], raw fp32.
#define GP 36
#define G_STAGE 9216                    // floats per stage (A 4608 + B 4608)
#define G_SMEM_FLOATS (3 * G_STAGE)     // 27648 floats = 110592 bytes

struct GArgs {
    const float* X[3];
    const float* W[3];
    const float* bias[3];
    float*       Y[3];
    int split;
};

__global__ __launch_bounds__(256) void gemm_tf32(GArgs ga)
{
    extern __shared__ float sg[];
    const uint32_t smb = smem_u32(sg);

    const int z = blockIdx.z;
    const float* __restrict__ X    = ga.X[z];
    const float* __restrict__ W    = ga.W[z];
    const float* __restrict__ bias = ga.bias[z];
    float* __restrict__       Y    = ga.Y[z];
    const int split = ga.split;

    const int t    = threadIdx.x;
    const int lane = t & 31;
    const int wid  = t >> 5;
    const int gid  = lane >> 2;
    const int tg   = lane & 3;

    const int bm = blockIdx.y * 128;
    const int bn = blockIdx.x * 128;
    const int m_base = (wid >> 1) * 32;
    const int n_base = (wid & 1) * 64;

    float acc[2][8][4];
    #pragma unroll
    for (int mt = 0; mt < 2; mt++)
        #pragma unroll
        for (int nt = 0; nt < 8; nt++)
            #pragma unroll
            for (int i = 0; i < 4; i++) acc[mt][nt][i] = 0.f;

    // prologue: prefetch chunks 0,1 into stages 0,1
    #pragma unroll
    for (int p = 0; p < 2; p++) {
        const int aoff = p * G_STAGE;
        const int boff = p * G_STAGE + 4608;
        const float* xs = X + (size_t)bm * DMODEL + p * 32;
        const float* ws = W + (size_t)bn * DMODEL + p * 32;
        #pragma unroll
        for (int l = 0; l < 4; l++) {
            int id = t + 256 * l;
            int r  = id >> 3, q = id & 7;
            cpa16(smb + (uint32_t)(aoff + r * GP + q * 4) * 4,
                  xs + (size_t)r * DMODEL + q * 4);
            cpa16(smb + (uint32_t)(boff + r * GP + q * 4) * 4,
                  ws + (size_t)r * DMODEL + q * 4);
        }
        CPA_COMMIT();
    }

    for (int c = 0; c < 32; c++) {
        // complete group c; at this point groups {c, c+1} are outstanding
        if (c + 1 < 32) { CPA_WAIT1(); } else { CPA_WAIT0(); }
        __syncthreads();   // all warps done with compute of c-1 (its stage = (c+2)%3)

        // prefetch chunk c+2 into stage (c+2)%3 (retired at iteration c-1)
        if (c + 2 < 32) {
            const int ns   = (c + 2) % 3;
            const int naof = ns * G_STAGE;
            const int nbof = ns * G_STAGE + 4608;
            const int k0   = (c + 2) * 32;
            const float* xs = X + (size_t)bm * DMODEL + k0;
            const float* ws = W + (size_t)bn * DMODEL + k0;
            #pragma unroll
            for (int l = 0; l < 4; l++) {
                int id = t + 256 * l;
                int r  = id >> 3, q = id & 7;
                cpa16(smb + (uint32_t)(naof + r * GP + q * 4) * 4,
                      xs + (size_t)r * DMODEL + q * 4);
                cpa16(smb + (uint32_t)(nbof + r * GP + q * 4) * 4,
                      ws + (size_t)r * DMODEL + q * 4);
            }
            CPA_COMMIT();
        }

        const int stage = c % 3;
        const float* As = sg + stage * G_STAGE;
        const float* Bs = sg + stage * G_STAGE + 4608;
        #pragma unroll
        for (int ks = 0; ks < 4; ks++) {
            const int kb = ks * 8;
            unsigned afr[2][4];
            #pragma unroll
            for (int mt = 0; mt < 2; mt++) {
                int m = m_base + mt * 16;
                afr[mt][0] = f2tf32(As[(m + gid    ) * GP + kb + tg    ]);
                afr[mt][1] = f2tf32(As[(m + gid + 8) * GP + kb + tg    ]);
                afr[mt][2] = f2tf32(As[(m + gid    ) * GP + kb + 4 + tg]);
                afr[mt][3] = f2tf32(As[(m + gid + 8) * GP + kb + 4 + tg]);
            }
            unsigned bfr[8][2];
            #pragma unroll
            for (int nt = 0; nt < 8; nt++) {
                int n = n_base + nt * 8;
                bfr[nt][0] = f2tf32(Bs[(n + gid) * GP + kb + tg    ]);
                bfr[nt][1] = f2tf32(Bs[(n + gid) * GP + kb + 4 + tg]);
            }
            #pragma unroll
            for (int mt = 0; mt < 2; mt++)
                #pragma unroll
                for (int nt = 0; nt < 8; nt++)
                    mma_tf32(acc[mt][nt], afr[mt], bfr[nt]);
        }
    }

    // epilogue
    #pragma unroll
    for (int nt = 0; nt < 8; nt++) {
        int c0 = bn + n_base + nt * 8 + tg * 2;
        float b0 = bias[c0], b1 = bias[c0 + 1];
        #pragma unroll
        for (int mt = 0; mt < 2; mt++) {
            int r0 = bm + m_base + mt * 16 + gid;
            #pragma unroll
            for (int half = 0; half < 2; half++) {
                int m = r0 + half * 8;
                float v0 = acc[mt][nt][half * 2 + 0] + b0;
                float v1 = acc[mt][nt][half * 2 + 1] + b1;
                if (!split) {
                    Y[(size_t)m * DMODEL + c0]     = v0;
                    Y[(size_t)m * DMODEL + c0 + 1] = v1;
                } else {
                    int b_ = m >> 11;
                    int s  = m & (SEQ - 1);
                    int h  = c0 >> 6;
                    int dh = c0 & (DHEAD - 1);
                    size_t base = (((size_t)(b_ * NHEADS + h)) * SEQ + s) * DHEAD;
                    Y[base + dh]     = cvt_tf32f(v0);   // pre-round for attn
                    Y[base + dh + 1] = cvt_tf32f(v1);
                }
            }
        }
    }
}

// ---------------- attention: register flash, 3-stage KV ring, 1 sync/iter --
// Q/K/V pre-rounded by QKV GEMM epilogue. Base-2 softmax.
#define KP 68
#define VP 72
#define A_STAGE 8960                    // K 64*68=4352 + V 64*72=4608
#define A_SMEM_FLOATS (3 * A_STAGE)     // 26880 floats = 107520 bytes

#define LOG2E 1.44269504088896340736f

__global__ __launch_bounds__(256) void attn_kernel(
    const float* __restrict__ Q, const float* __restrict__ K,
    const float* __restrict__ V, float* __restrict__ O)
{
    extern __shared__ float sm[];
    const uint32_t smb = smem_u32(sm);

    const int t    = threadIdx.x;
    const int lane = t & 31;
    const int wid  = t >> 5;
    const int gid  = lane >> 2;
    const int tg   = lane & 3;

    const int b  = blockIdx.z, h = blockIdx.y;
    const int q0 = blockIdx.x << 7;
    const size_t head_base = ((size_t)(b * NHEADS + h)) * SEQ * DHEAD;

    // ---- stage Q (scaled 0.125*log2e, tf32) into smem (aliases stage 0/1) --
    {
        float (*Qs)[KP] = (float (*)[KP])sm;
        const float qs = 0.125f * LOG2E;
        #pragma unroll
        for (int l = 0; l < 8; l++) {
            int id = t + 256 * l;
            int r  = id >> 4;
            int d4 = (id & 15) << 2;
            float4 v = *(const float4*)&Q[head_base + (size_t)(q0 + r) * DHEAD + d4];
            Qs[r][d4+0] = cvt_tf32f(v.x * qs);
            Qs[r][d4+1] = cvt_tf32f(v.y * qs);
            Qs[r][d4+2] = cvt_tf32f(v.z * qs);
            Qs[r][d4+3] = cvt_tf32f(v.w * qs);
        }
    }
    __syncthreads();

    unsigned qf[8][4];
    {
        float (*Qs)[KP] = (float (*)[KP])sm;
        const int wrow = wid * 16;
        #pragma unroll
        for (int ks = 0; ks < 8; ks++) {
            const int kb = ks * 8;
            qf[ks][0] = __float_as_uint(Qs[wrow + gid    ][kb + tg    ]);
            qf[ks][1] = __float_as_uint(Qs[wrow + gid + 8][kb + tg    ]);
            qf[ks][2] = __float_as_uint(Qs[wrow + gid    ][kb + 4 + tg]);
            qf[ks][3] = __float_as_uint(Qs[wrow + gid + 8][kb + 4 + tg]);
        }
    }
    __syncthreads();   // Q reads complete before KV prefetch overwrites staging

    // ---- prologue: prefetch KV tiles 0,1 into stages 0,1 ----
    #pragma unroll
    for (int p = 0; p < 2; p++) {
        const int koff = p * A_STAGE;
        const int voff = p * A_STAGE + 4352;
        const size_t gofs = head_base + (size_t)p * 64 * DHEAD;
        #pragma unroll
        for (int l = 0; l < 4; l++) {
            int id = t + 256 * l;
            int r  = id >> 4;
            int c4 = (id & 15) << 2;
            cpa16(smb + (uint32_t)(koff + r * KP + c4) * 4,
                  K + gofs + (size_t)r * DHEAD + c4);
            cpa16(smb + (uint32_t)(voff + r * VP + c4) * 4,
                  V + gofs + (size_t)r * DHEAD + c4);
        }
        CPA_COMMIT();
    }

    float oacc[8][4];
    #pragma unroll
    for (int nt = 0; nt < 8; nt++)
        #pragma unroll
        for (int i = 0; i < 4; i++) oacc[nt][i] = 0.f;
    float m0 = -1e30f, m1 = -1e30f, l0 = 0.f, l1 = 0.f;

    const int src1 = (lane & ~3) | (tg >> 1);
    const int src2 = src1 + 2;
    const bool odd = (tg & 1);

    const int NIT = SEQ / 64;   // 32
    for (int it = 0; it < NIT; it++) {
        if (it + 1 < NIT) { CPA_WAIT1(); } else { CPA_WAIT0(); }
        __syncthreads();   // all warps past compute of it-1 (stage (it+2)%3)

        // prefetch KV tile it+2 into stage retired last iteration
        if (it + 2 < NIT) {
            const int ns   = (it + 2) % 3;
            const int nk   = ns * A_STAGE;
            const int nv   = ns * A_STAGE + 4352;
            const size_t gofs = head_base + (size_t)(it + 2) * 64 * DHEAD;
            #pragma unroll
            for (int l = 0; l < 4; l++) {
                int id = t + 256 * l;
                int r  = id >> 4;
                int c4 = (id & 15) << 2;
                cpa16(smb + (uint32_t)(nk + r * KP + c4) * 4,
                      K + gofs + (size_t)r * DHEAD + c4);
                cpa16(smb + (uint32_t)(nv + r * VP + c4) * 4,
                      V + gofs + (size_t)r * DHEAD + c4);
            }
            CPA_COMMIT();
        }

        const int stage = it % 3;
        const float* Ks = sm + stage * A_STAGE;
        const float* Vs = sm + stage * A_STAGE + 4352;

        // ---- S2 = (Q*0.125*log2e) K^T ----
        float sacc[8][4];
        #pragma unroll
        for (int nt = 0; nt < 8; nt++)
            #pragma unroll
            for (int i = 0; i < 4; i++) sacc[nt][i] = 0.f;

        #pragma unroll
        for (int ks = 0; ks < 8; ks++) {
            const int kb = ks * 8;
            unsigned bfr[8][2];
            #pragma unroll
            for (int nt = 0; nt < 8; nt++) {
                bfr[nt][0] = __float_as_uint(Ks[(nt * 8 + gid) * KP + kb + tg    ]);
                bfr[nt][1] = __float_as_uint(Ks[(nt * 8 + gid) * KP + kb + 4 + tg]);
            }
            #pragma unroll
            for (int nt = 0; nt < 8; nt++)
                mma_tf32(sacc[nt], qf[ks], bfr[nt]);
        }

        // ---- online softmax, base-2 (regs + quad shuffles) ----
        float mx0 = -1e30f, mx1 = -1e30f;
        #pragma unroll
        for (int nt = 0; nt < 8; nt++) {
            mx0 = fmaxf(mx0, fmaxf(sacc[nt][0], sacc[nt][1]));
            mx1 = fmaxf(mx1, fmaxf(sacc[nt][2], sacc[nt][3]));
        }
        mx0 = fmaxf(mx0, __shfl_xor_sync(0xffffffffu, mx0, 1));
        mx0 = fmaxf(mx0, __shfl_xor_sync(0xffffffffu, mx0, 2));
        mx1 = fmaxf(mx1, __shfl_xor_sync(0xffffffffu, mx1, 1));
        mx1 = fmaxf(mx1, __shfl_xor_sync(0xffffffffu, mx1, 2));

        float m0n = fmaxf(m0, mx0), m1n = fmaxf(m1, mx1);
        float sc0 = exp2f(m0 - m0n), sc1 = exp2f(m1 - m1n);
        m0 = m0n; m1 = m1n;

        float s0 = 0.f, s1 = 0.f;
        #pragma unroll
        for (int nt = 0; nt < 8; nt++) {
            sacc[nt][0] = exp2f(sacc[nt][0] - m0); s0 += sacc[nt][0];
            sacc[nt][1] = exp2f(sacc[nt][1] - m0); s0 += sacc[nt][1];
            sacc[nt][2] = exp2f(sacc[nt][2] - m1); s1 += sacc[nt][2];
            sacc[nt][3] = exp2f(sacc[nt][3] - m1); s1 += sacc[nt][3];
        }
        s0 += __shfl_xor_sync(0xffffffffu, s0, 1);
        s0 += __shfl_xor_sync(0xffffffffu, s0, 2);
        s1 += __shfl_xor_sync(0xffffffffu, s1, 1);
        s1 += __shfl_xor_sync(0xffffffffu, s1, 2);
        l0 = l0 * sc0 + s0;
        l1 = l1 * sc1 + s1;

        #pragma unroll
        for (int nt = 0; nt < 8; nt++) {
            oacc[nt][0] *= sc0; oacc[nt][1] *= sc0;
            oacc[nt][2] *= sc1; oacc[nt][3] *= sc1;
        }

        // ---- PV: P c-frag -> a-frag via quad shuffles, mma with V ----
        #pragma unroll
        for (int ks = 0; ks < 8; ks++) {
            float p0 = sacc[ks][0], p1 = sacc[ks][1];
            float p2 = sacc[ks][2], p3 = sacc[ks][3];
            float v00 = __shfl_sync(0xffffffffu, p0, src1);
            float v01 = __shfl_sync(0xffffffffu, p1, src1);
            float v10 = __shfl_sync(0xffffffffu, p2, src1);
            float v11 = __shfl_sync(0xffffffffu, p3, src1);
            float v20 = __shfl_sync(0xffffffffu, p0, src2);
            float v21 = __shfl_sync(0xffffffffu, p1, src2);
            float v30 = __shfl_sync(0xffffffffu, p2, src2);
            float v31 = __shfl_sync(0xffffffffu, p3, src2);
            unsigned a[4];
            a[0] = f2tf32(odd ? v01 : v00);
            a[1] = f2tf32(odd ? v11 : v10);
            a[2] = f2tf32(odd ? v21 : v20);
            a[3] = f2tf32(odd ? v31 : v30);

            const int kb = ks * 8;
            #pragma unroll
            for (int nt = 0; nt < 8; nt++) {
                unsigned b2[2];
                b2[0] = __float_as_uint(Vs[(kb + tg    ) * VP + nt * 8 + gid]);
                b2[1] = __float_as_uint(Vs[(kb + 4 + tg) * VP + nt * 8 + gid]);
                mma_tf32(oacc[nt], a, b2);
            }
        }
    }

    // ---- epilogue: normalize, write rounded [B,S,D] (O-proj input) ----
    {
        float il0 = 1.0f / l0, il1 = 1.0f / l1;
        int r0 = q0 + wid * 16 + gid;
        int r1 = r0 + 8;
        #pragma unroll
        for (int nt = 0; nt < 8; nt++) {
            int c = h * DHEAD + nt * 8 + tg * 2;
            float2 o0 = make_float2(cvt_tf32f(oacc[nt][0] * il0),
                                    cvt_tf32f(oacc[nt][1] * il0));
            float2 o1 = make_float2(cvt_tf32f(oacc[nt][2] * il1),
                                    cvt_tf32f(oacc[nt][3] * il1));
            *(float2*)&O[((size_t)(b * SEQ + r0)) * DMODEL + c] = o0;
            *(float2*)&O[((size_t)(b * SEQ + r1)) * DMODEL + c] = o1;
        }
    }
}

extern "C" void kernel_launch(void* const* d_in, const int* in_sizes, int n_in,
                              void* d_out, int out_size)
{
    const float* query = (const float*)d_in[0];
    const float* key_  = (const float*)d_in[1];
    const float* value = (const float*)d_in[2];
    const float* Wq = (const float*)d_in[3];
    const float* bq = (const float*)d_in[4];
    const float* Wk = (const float*)d_in[5];
    const float* bk = (const float*)d_in[6];
    const float* Wv = (const float*)d_in[7];
    const float* bv = (const float*)d_in[8];
    const float* Wo = (const float*)d_in[9];
    const float* bo = (const float*)d_in[10];

    float *qptr, *kptr, *vptr, *aoptr;
    cudaGetSymbolAddress((void**)&qptr,  g_q);
    cudaGetSymbolAddress((void**)&kptr,  g_k);
    cudaGetSymbolAddress((void**)&vptr,  g_v);
    cudaGetSymbolAddress((void**)&aoptr, g_ao);

    const int gemm_smem = G_SMEM_FLOATS * sizeof(float);   // 110592
    const int attn_smem = A_SMEM_FLOATS * sizeof(float);   // 107520
    cudaFuncSetAttribute(gemm_tf32, cudaFuncAttributeMaxDynamicSharedMemorySize, gemm_smem);
    cudaFuncSetAttribute(attn_kernel, cudaFuncAttributeMaxDynamicSharedMemorySize, attn_smem);

    // fused QKV projections (grid.z selects matrix)
    GArgs qkv;
    qkv.X[0] = query; qkv.W[0] = Wq; qkv.bias[0] = bq; qkv.Y[0] = qptr;
    qkv.X[1] = key_;  qkv.W[1] = Wk; qkv.bias[1] = bk; qkv.Y[1] = kptr;
    qkv.X[2] = value; qkv.W[2] = Wv; qkv.bias[2] = bv; qkv.Y[2] = vptr;
    qkv.split = 1;
    dim3 qkvgrid(DMODEL / 128, MROWS / 128, 3);   // (8, 32, 3)
    gemm_tf32<<<qkvgrid, 256, gemm_smem>>>(qkv);

    dim3 agrid(SEQ / 128, NHEADS, BATCH);         // (16, 16, 2)
    attn_kernel<<<agrid, 256, attn_smem>>>(qptr, kptr, vptr, aoptr);

    GArgs og;
    og.X[0] = aoptr; og.W[0] = Wo; og.bias[0] = bo; og.Y[0] = (float*)d_out;
    og.X[1] = aoptr; og.W[1] = Wo; og.bias[1] = bo; og.Y[1] = (float*)d_out;
    og.X[2] = aoptr; og.W[2] = Wo; og.bias[2] = bo; og.Y[2] = (float*)d_out;
    og.split = 0;
    dim3 ogrid(DMODEL / 128, MROWS / 128, 1);     // (8, 32, 1)
    gemm_tf32<<<ogrid, 256, gemm_smem>>>(og);
}